// round 1
// baseline (speedup 1.0000x reference)
#include <cuda_runtime.h>
#include <math.h>

#define BB 16
#define NN 8
#define TT 65536
#define CHUNKS 32
#define TPB 256
#define TPC (TT / CHUNKS)        // 2048 floats per block per row
#define K4 (TPC / (4 * TPB))     // 2 float4 iterations per thread

// Scratch for partial (x_i - y_j)^2 sums: [B][N][N]
__device__ float g_acc[BB * NN * NN];

__global__ void sp_zero() {
    int i = threadIdx.x;
    if (i < BB * NN * NN) g_acc[i] = 0.f;
}

// Pairwise squared-difference accumulation.
// Grid: (CHUNKS, BB). Each block handles one batch and one contiguous t-chunk,
// reading every element of that chunk exactly once (all 64 pairs in registers).
__global__ __launch_bounds__(TPB, 2)
void sp_pair(const float* __restrict__ inp, const float* __restrict__ tgt) {
    const int b = blockIdx.y;
    const int chunk = blockIdx.x;

    const float4* __restrict__ X = reinterpret_cast<const float4*>(inp)
                                   + (size_t)b * NN * (TT / 4) + (size_t)chunk * (TPC / 4);
    const float4* __restrict__ Y = reinterpret_cast<const float4*>(tgt)
                                   + (size_t)b * NN * (TT / 4) + (size_t)chunk * (TPC / 4);

    float acc[NN][NN];
#pragma unroll
    for (int i = 0; i < NN; i++)
#pragma unroll
        for (int j = 0; j < NN; j++) acc[i][j] = 0.f;

#pragma unroll
    for (int k = 0; k < K4; k++) {
        const int t4 = threadIdx.x + k * TPB;
        float4 x[NN];
#pragma unroll
        for (int i = 0; i < NN; i++) x[i] = __ldg(&X[(size_t)i * (TT / 4) + t4]);
#pragma unroll
        for (int j = 0; j < NN; j++) {
            const float4 y = __ldg(&Y[(size_t)j * (TT / 4) + t4]);
#pragma unroll
            for (int i = 0; i < NN; i++) {
                float d0 = x[i].x - y.x;
                float d1 = x[i].y - y.y;
                float d2 = x[i].z - y.z;
                float d3 = x[i].w - y.w;
                acc[i][j] += d0 * d0 + d1 * d1 + d2 * d2 + d3 * d3;
            }
        }
    }

    // Warp tree-reduce each of the 64 accumulators.
#pragma unroll
    for (int i = 0; i < NN; i++)
#pragma unroll
        for (int j = 0; j < NN; j++) {
            float v = acc[i][j];
            v += __shfl_xor_sync(0xffffffffu, v, 16);
            v += __shfl_xor_sync(0xffffffffu, v, 8);
            v += __shfl_xor_sync(0xffffffffu, v, 4);
            v += __shfl_xor_sync(0xffffffffu, v, 2);
            v += __shfl_xor_sync(0xffffffffu, v, 1);
            acc[i][j] = v;
        }

    __shared__ float sred[TPB / 32][NN * NN];
    const int warp = threadIdx.x >> 5;
    const int lane = threadIdx.x & 31;
    if (lane == 0) {
#pragma unroll
        for (int i = 0; i < NN; i++)
#pragma unroll
            for (int j = 0; j < NN; j++) sred[warp][i * NN + j] = acc[i][j];
    }
    __syncthreads();

    if (threadIdx.x < NN * NN) {
        float s = 0.f;
#pragma unroll
        for (int w = 0; w < TPB / 32; w++) s += sred[w][threadIdx.x];
        atomicAdd(&g_acc[b * NN * NN + threadIdx.x], s);
    }
}

// Sinkhorn-Knopp (10 iters) + loss + argmax. One warp; thread b owns batch b.
__global__ void sp_finish(float* __restrict__ out, int out_size) {
    const int b = threadIdx.x;
    float loss_b = 0.f;
    int pat[NN];
#pragma unroll
    for (int i = 0; i < NN; i++) pat[i] = 0;

    float pl[NN][NN];
    float Z[NN][NN];

    if (b < BB) {
#pragma unroll
        for (int i = 0; i < NN; i++)
#pragma unroll
            for (int j = 0; j < NN; j++) {
                float v = g_acc[b * NN * NN + i * NN + j] * (1.0f / (float)TT);
                pl[i][j] = v;
                Z[i][j] = -v;  // COLDNESS = 1
            }

#pragma unroll 1
        for (int it = 0; it < 10; it++) {
            // logsumexp over axis=1 (over i), per column j
#pragma unroll
            for (int j = 0; j < NN; j++) {
                float m = Z[0][j];
#pragma unroll
                for (int i = 1; i < NN; i++) m = fmaxf(m, Z[i][j]);
                float s = 0.f;
#pragma unroll
                for (int i = 0; i < NN; i++) s += expf(Z[i][j] - m);
                float l = m + logf(s);
#pragma unroll
                for (int i = 0; i < NN; i++) Z[i][j] -= l;
            }
            // logsumexp over axis=2 (over j), per row i
#pragma unroll
            for (int i = 0; i < NN; i++) {
                float m = Z[i][0];
#pragma unroll
                for (int j = 1; j < NN; j++) m = fmaxf(m, Z[i][j]);
                float s = 0.f;
#pragma unroll
                for (int j = 0; j < NN; j++) s += expf(Z[i][j] - m);
                float l = m + logf(s);
#pragma unroll
                for (int j = 0; j < NN; j++) Z[i][j] -= l;
            }
        }

        // loss_b = sum (pl + Z) * exp(Z); pattern = argmax_j Z
#pragma unroll
        for (int i = 0; i < NN; i++) {
            float best = Z[i][0];
            int bj = 0;
#pragma unroll
            for (int j = 1; j < NN; j++)
                if (Z[i][j] > best) { best = Z[i][j]; bj = j; }
            pat[i] = bj;
#pragma unroll
            for (int j = 0; j < NN; j++)
                loss_b += (pl[i][j] + Z[i][j]) * expf(Z[i][j]);
        }
    }

    // Reduce loss over 16 active lanes (inactive lanes contribute 0).
    float s = loss_b;
#pragma unroll
    for (int o = 16; o; o >>= 1) s += __shfl_xor_sync(0xffffffffu, s, o);
    const float loss = s * (1.0f / (float)BB);

    const int full = 1 + BB * NN;  // 129: loss followed by pattern
    if (out_size >= full) {
        if (threadIdx.x == 0) out[0] = loss;
        if (b < BB) {
#pragma unroll
            for (int i = 0; i < NN; i++) out[1 + b * NN + i] = (float)pat[i];
        }
        // Defensive: clear any remaining poisoned tail.
        for (int idx = full + (int)threadIdx.x; idx < out_size; idx += 32) out[idx] = 0.f;
    } else if (out_size == BB * NN) {
        if (b < BB) {
#pragma unroll
            for (int i = 0; i < NN; i++) out[b * NN + i] = (float)pat[i];
        }
    } else {
        if (threadIdx.x == 0 && out_size > 0) out[0] = loss;
        for (int idx = 1 + (int)threadIdx.x; idx < out_size; idx += 32) out[idx] = 0.f;
    }
}

extern "C" void kernel_launch(void* const* d_in, const int* in_sizes, int n_in,
                              void* d_out, int out_size) {
    const float* inp = (const float*)d_in[0];
    const float* tgt = (const float*)d_in[1];

    sp_zero<<<1, BB * NN * NN>>>();
    dim3 grid(CHUNKS, BB);
    sp_pair<<<grid, TPB>>>(inp, tgt);
    sp_finish<<<1, 32>>>((float*)d_out, out_size);
}